// round 13
// baseline (speedup 1.0000x reference)
#include <cuda_runtime.h>
#include <cuda_bf16.h>
#include <stdint.h>

#define IN_F 256
#define HF   128
#define NC   64
#define MAX_NODES 10000
#define MAX_EDGES 640000
#define PAD 192   // max supported degree; Poisson(64) tail at 192 is ~1e-60

typedef unsigned long long ull;
typedef long long ll;

// ---------------- scratch (static device globals; no allocation) -------------
// All activations live ONLY as split bf16 (hi + lo); no fp32 copies.
__device__ __nv_bfloat16 g_xhi[MAX_NODES * IN_F];
__device__ __nv_bfloat16 g_xlo[MAX_NODES * IN_F];
__device__ __nv_bfloat16 g_h0hi[MAX_NODES * HF];
__device__ __nv_bfloat16 g_h0lo[MAX_NODES * HF];
__device__ __nv_bfloat16 g_h1hi[MAX_NODES * HF];
__device__ __nv_bfloat16 g_h1lo[MAX_NODES * HF];
__device__ __nv_bfloat16 g_h2hi[MAX_NODES * HF];
__device__ __nv_bfloat16 g_h2lo[MAX_NODES * HF];
__device__ __nv_bfloat16 g_mhi[MAX_NODES * HF];
__device__ __nv_bfloat16 g_mlo[MAX_NODES * HF];
__device__ int g_cnt[MAX_NODES];
__device__ int g_csr[MAX_NODES * PAD];

// Persistent split-bf16 weights
#define OFF_LIN 0
#define OFF_L1  32768
#define OFF_R1  49152
#define OFF_L2  65536
#define OFF_R2  81920
#define OFF_CLS 98304
#define TOTW    106496
__device__ __nv_bfloat16 g_Whi[TOTW];
__device__ __nv_bfloat16 g_Wlo[TOTW];

// ---------------- init: zero counters + split weights --------------------------
__global__ void init_kernel(const float* __restrict__ wlin,
                            const float* __restrict__ wl1, const float* __restrict__ wr1,
                            const float* __restrict__ wl2, const float* __restrict__ wr2,
                            const float* __restrict__ wcls, int n_nodes) {
    int i = blockIdx.x * blockDim.x + threadIdx.x;
    if (i < n_nodes) g_cnt[i] = 0;
    if (i >= TOTW) return;
    const float* src; int off;
    if (i < OFF_L1)       { src = wlin; off = OFF_LIN; }
    else if (i < OFF_L2)  { if (i < OFF_R1) { src = wl1; off = OFF_L1; } else { src = wr1; off = OFF_R1; } }
    else if (i < OFF_CLS) { if (i < OFF_R2) { src = wl2; off = OFF_L2; } else { src = wr2; off = OFF_R2; } }
    else                  { src = wcls; off = OFF_CLS; }
    float x = src[i - off];
    __nv_bfloat16 h = __float2bfloat16_rn(x);
    g_Whi[i] = h;
    g_Wlo[i] = __float2bfloat16_rn(x - __bfloat162float(h));
}

// ---------------- x split: fp32 -> bf16 hi/lo ---------------------------------
__device__ __forceinline__ uint32_t bpack(float a, float b) {
    return (uint32_t)__bfloat16_as_ushort(__float2bfloat16_rn(a)) |
           ((uint32_t)__bfloat16_as_ushort(__float2bfloat16_rn(b)) << 16);
}
__global__ void xsplit_kernel(const float* __restrict__ x, int n4) {
    int i = blockIdx.x * blockDim.x + threadIdx.x;
    if (i >= n4) return;
    float4 v = ((const float4*)x)[i];
    __nv_bfloat16 h0 = __float2bfloat16_rn(v.x), h1 = __float2bfloat16_rn(v.y);
    __nv_bfloat16 h2 = __float2bfloat16_rn(v.z), h3 = __float2bfloat16_rn(v.w);
    uint2 hi, lo;
    hi.x = (uint32_t)__bfloat16_as_ushort(h0) | ((uint32_t)__bfloat16_as_ushort(h1) << 16);
    hi.y = (uint32_t)__bfloat16_as_ushort(h2) | ((uint32_t)__bfloat16_as_ushort(h3) << 16);
    lo.x = bpack(v.x - __bfloat162float(h0), v.y - __bfloat162float(h1));
    lo.y = bpack(v.z - __bfloat162float(h2), v.w - __bfloat162float(h3));
    ((uint2*)g_xhi)[i] = hi;
    ((uint2*)g_xlo)[i] = lo;
}

// ---------------- scatter with inline dtype detect -----------------------------
__global__ void scatter_kernel(const void* ei, int E, int n_nodes) {
    const long long* p64 = (const long long*)ei;
    long long v = p64[threadIdx.x & 255];
    int ok = (v >= 0 && v < (long long)n_nodes) ? 1 : 0;
    int is64 = __syncthreads_and(ok);

    int e = blockIdx.x * blockDim.x + threadIdx.x;
    if (e >= E) return;
    int src, dst;
    if (is64) {
        src = (int)p64[e];
        dst = (int)p64[(ll)E + e];
    } else {
        src = ((const int*)ei)[e];
        dst = ((const int*)ei)[E + e];
    }
    int pos = atomicAdd(&g_cnt[dst], 1);
    if (pos < PAD) g_csr[dst * PAD + pos] = src;
}

// ---------------- mean aggregation over hi copy; writes split mean -------------
__device__ __forceinline__ float blo(uint32_t u) { return __uint_as_float(u << 16); }
__device__ __forceinline__ float bhi(uint32_t u) { return __uint_as_float(u & 0xffff0000u); }

__global__ void __launch_bounds__(256)
agg_b16(const __nv_bfloat16* __restrict__ hb,
        __nv_bfloat16* __restrict__ mhi, __nv_bfloat16* __restrict__ mlo, int n) {
    int warp = (blockIdx.x * blockDim.x + threadIdx.x) >> 5;
    int lane = threadIdx.x & 31;
    if (warp >= n) return;
    int deg = g_cnt[warp];
    int end = deg < PAD ? deg : PAD;
    const int* lst = &g_csr[warp * PAD];
    const uint2* p = (const uint2*)hb;   // row = 32 uint2 (4 bf16 each)

    float a00=0,a01=0,a02=0,a03=0, a10=0,a11=0,a12=0,a13=0;
    float a20=0,a21=0,a22=0,a23=0, a30=0,a31=0,a32=0,a33=0;

    int e = 0;
    for (; e + 7 < end; e += 8) {
        int4 A = *(const int4*)&lst[e];
        int4 B = *(const int4*)&lst[e + 4];
        uint2 v0 = p[(ll)A.x * 32 + lane];
        uint2 v1 = p[(ll)A.y * 32 + lane];
        uint2 v2 = p[(ll)A.z * 32 + lane];
        uint2 v3 = p[(ll)A.w * 32 + lane];
        uint2 v4 = p[(ll)B.x * 32 + lane];
        uint2 v5 = p[(ll)B.y * 32 + lane];
        uint2 v6 = p[(ll)B.z * 32 + lane];
        uint2 v7 = p[(ll)B.w * 32 + lane];
        a00 += blo(v0.x); a01 += bhi(v0.x); a02 += blo(v0.y); a03 += bhi(v0.y);
        a10 += blo(v1.x); a11 += bhi(v1.x); a12 += blo(v1.y); a13 += bhi(v1.y);
        a20 += blo(v2.x); a21 += bhi(v2.x); a22 += blo(v2.y); a23 += bhi(v2.y);
        a30 += blo(v3.x); a31 += bhi(v3.x); a32 += blo(v3.y); a33 += bhi(v3.y);
        a00 += blo(v4.x); a01 += bhi(v4.x); a02 += blo(v4.y); a03 += bhi(v4.y);
        a10 += blo(v5.x); a11 += bhi(v5.x); a12 += blo(v5.y); a13 += bhi(v5.y);
        a20 += blo(v6.x); a21 += bhi(v6.x); a22 += blo(v6.y); a23 += bhi(v6.y);
        a30 += blo(v7.x); a31 += bhi(v7.x); a32 += blo(v7.y); a33 += bhi(v7.y);
    }
    for (; e + 3 < end; e += 4) {
        int4 A = *(const int4*)&lst[e];
        uint2 v0 = p[(ll)A.x * 32 + lane];
        uint2 v1 = p[(ll)A.y * 32 + lane];
        uint2 v2 = p[(ll)A.z * 32 + lane];
        uint2 v3 = p[(ll)A.w * 32 + lane];
        a00 += blo(v0.x); a01 += bhi(v0.x); a02 += blo(v0.y); a03 += bhi(v0.y);
        a10 += blo(v1.x); a11 += bhi(v1.x); a12 += blo(v1.y); a13 += bhi(v1.y);
        a20 += blo(v2.x); a21 += bhi(v2.x); a22 += blo(v2.y); a23 += bhi(v2.y);
        a30 += blo(v3.x); a31 += bhi(v3.x); a32 += blo(v3.y); a33 += bhi(v3.y);
    }
    for (; e < end; e++) {
        int j0 = lst[e];
        uint2 v0 = p[(ll)j0 * 32 + lane];
        a00 += blo(v0.x); a01 += bhi(v0.x); a02 += blo(v0.y); a03 += bhi(v0.y);
    }
    float s = 1.0f / (float)(deg > 1 ? deg : 1);
    float r0 = (a00+a10+a20+a30)*s, r1 = (a01+a11+a21+a31)*s;
    float r2 = (a02+a12+a22+a32)*s, r3 = (a03+a13+a23+a33)*s;

    __nv_bfloat16 b0 = __float2bfloat16_rn(r0), b1 = __float2bfloat16_rn(r1);
    __nv_bfloat16 b2 = __float2bfloat16_rn(r2), b3 = __float2bfloat16_rn(r3);
    uint2 hi, lo;
    hi.x = (uint32_t)__bfloat16_as_ushort(b0) | ((uint32_t)__bfloat16_as_ushort(b1) << 16);
    hi.y = (uint32_t)__bfloat16_as_ushort(b2) | ((uint32_t)__bfloat16_as_ushort(b3) << 16);
    lo.x = bpack(r0 - __bfloat162float(b0), r1 - __bfloat162float(b1));
    lo.y = bpack(r2 - __bfloat162float(b2), r3 - __bfloat162float(b3));
    ((uint2*)mhi)[(ll)warp * 32 + lane] = hi;
    ((uint2*)mlo)[(ll)warp * 32 + lane] = lo;
}

// ---------------- split-bf16 MMA GEMM: pre-split A via cp.async ----------------
#define MMA_BF16(c, a0,a1,a2,a3, b0,b1) \
    asm volatile("mma.sync.aligned.m16n8k16.row.col.f32.bf16.bf16.f32 " \
        "{%0,%1,%2,%3}, {%4,%5,%6,%7}, {%8,%9}, {%0,%1,%2,%3};" \
        : "+f"(c[0]), "+f"(c[1]), "+f"(c[2]), "+f"(c[3]) \
        : "r"(a0), "r"(a1), "r"(a2), "r"(a3), "r"(b0), "r"(b1))

#define LDSM_X4(r0,r1,r2,r3, addr) \
    asm volatile("ldmatrix.sync.aligned.m8n8.x4.shared.b16 {%0,%1,%2,%3}, [%4];" \
        : "=r"(r0), "=r"(r1), "=r"(r2), "=r"(r3) : "r"(addr))
#define LDSM_X2(r0,r1, addr) \
    asm volatile("ldmatrix.sync.aligned.m8n8.x2.shared.b16 {%0,%1}, [%2];" \
        : "=r"(r0), "=r"(r1) : "r"(addr))

#define CPA16(dst, src) \
    asm volatile("cp.async.cg.shared.global [%0], [%1], 16;" \
        :: "r"(dst), "l"(src) : "memory")

#define PADW 20   // u32 per 32k W row (16 + 4 pad)

// KN = full output width (row stride of C/Chi); block covers 64 cols at n0.
template<int KN, int KV, bool DUAL, bool RELU_OUT, bool HAS_BIAS, bool SPLIT_OUT>
__global__ void __launch_bounds__(256, 2)
mma_gemm(const __nv_bfloat16* __restrict__ Ah1, const __nv_bfloat16* __restrict__ Al1,
         const __nv_bfloat16* __restrict__ Ah2, const __nv_bfloat16* __restrict__ Al2,
         int woff1, int woff2, const float* __restrict__ bias,
         float* __restrict__ C, __nv_bfloat16* __restrict__ Chi,
         __nv_bfloat16* __restrict__ Clo, int M) {
    const int BM    = 64;
    const int ASTRB = KV * 2 + 16;     // bytes per A smem row (== old layout)
    const int ASZB  = BM * ASTRB;
    const int WBUF  = 64 * PADW;
    const int NCH   = KV / 32;
    const int KA    = DUAL ? KV / 2 : KV;

    extern __shared__ uint32_t sm[];
    char*     As_hi = (char*)sm;
    char*     As_lo = As_hi + ASZB;
    uint32_t* Wh    = (uint32_t*)(As_lo + ASZB);
    uint32_t* Wl    = Wh + WBUF;

    int tid  = threadIdx.x;
    int wid  = tid >> 5;
    int lane = tid & 31;
    int g    = lane >> 2;
    int t    = lane & 3;
    int wm   = wid >> 2;   // 0..1 : 32 rows each
    int wn   = wid & 3;    // 0..3 : 16 cols each
    int m0   = blockIdx.x * BM;
    int n0   = blockIdx.y * 64;

    // W chunk register prefetch
    uint4 rh, rl;
    int w_nn = tid >> 2, w_q = tid & 3;
    auto ldregs = [&](int c) {
        int k = c * 32 + w_q * 8;
        int wo = woff1, kk = k;
        if (DUAL && k >= KV / 2) { wo = woff2; kk = k - KV / 2; }
        int si = (n0 + w_nn) * KA + kk + wo;
        rh = *(const uint4*)&g_Whi[si];
        rl = *(const uint4*)&g_Wlo[si];
    };
    auto streg = [&]() {
        *(uint4*)&Wh[w_nn * PADW + w_q * 4] = rh;
        *(uint4*)&Wl[w_nn * PADW + w_q * 4] = rl;
    };

    ldregs(0);

    // ---- A tile: async-copy pre-split hi/lo (no conversion math) ------------
    uint32_t aHiB = (uint32_t)__cvta_generic_to_shared(As_hi);
    uint32_t aLoB = aHiB + (uint32_t)ASZB;
    const int C16 = KV * 2 / 16;                  // 16B chunks per row
#pragma unroll
    for (int it = 0; it < BM * C16 / 256; it++) {
        int f    = tid + it * 256;
        int row  = f / C16;
        int c16  = f % C16;
        int kel  = c16 * 8;                       // first bf16 element
        int gm   = m0 + row;
        const __nv_bfloat16* sh = Ah1;
        const __nv_bfloat16* sl = Al1;
        int kk = kel;
        if (DUAL && kel >= KV / 2) { sh = Ah2; sl = Al2; kk = kel - KV / 2; }
        if (gm < M) {
            CPA16(aHiB + row * ASTRB + c16 * 16, sh + (ll)gm * KA + kk);
            CPA16(aLoB + row * ASTRB + c16 * 16, sl + (ll)gm * KA + kk);
        } else {
            uint4 z = make_uint4(0, 0, 0, 0);
            *(uint4*)(As_hi + row * ASTRB + c16 * 16) = z;
            *(uint4*)(As_lo + row * ASTRB + c16 * 16) = z;
        }
    }
    asm volatile("cp.async.commit_group;" ::: "memory");

    // ldmatrix per-thread address precomputation (byte layout == old kernel)
    uint32_t wHiB = (uint32_t)__cvta_generic_to_shared(Wh);
    uint32_t wLoB = (uint32_t)__cvta_generic_to_shared(Wl);
    int amat = lane >> 3, ar = lane & 7;
    uint32_t aOff[2];
#pragma unroll
    for (int mf = 0; mf < 2; mf++)
        aOff[mf] = (uint32_t)((wm * 32 + mf * 16 + (amat & 1) * 8 + ar) * ASTRB
                              + (amat >> 1) * 16);
    int blx = lane & 15;
    int bmat = blx >> 3, br = blx & 7;
    uint32_t bOff[2];
#pragma unroll
    for (int nf = 0; nf < 2; nf++)
        bOff[nf] = (uint32_t)((wn * 16 + nf * 8 + br) * (PADW * 4) + bmat * 16);

    float c_[2][2][4];
#pragma unroll
    for (int i = 0; i < 2; i++)
#pragma unroll
        for (int j = 0; j < 2; j++)
#pragma unroll
            for (int q = 0; q < 4; q++) c_[i][j][q] = 0.f;

    streg();
    asm volatile("cp.async.wait_group 0;" ::: "memory");
    __syncthreads();

#pragma unroll
    for (int c = 0; c < NCH; c++) {
        if (c + 1 < NCH) ldregs(c + 1);
#pragma unroll
        for (int ko = 0; ko < 2; ko++) {
            uint32_t kbyte = (uint32_t)((c * 16 + ko * 8) * 4);
            uint32_t kwb   = (uint32_t)(ko * 8 * 4);
            uint32_t bh0[2], bh1[2], bl0[2], bl1[2];
#pragma unroll
            for (int nf = 0; nf < 2; nf++) {
                LDSM_X2(bh0[nf], bh1[nf], wHiB + bOff[nf] + kwb);
                LDSM_X2(bl0[nf], bl1[nf], wLoB + bOff[nf] + kwb);
            }
#pragma unroll
            for (int mf = 0; mf < 2; mf++) {
                uint32_t ah0, ah1, ah2, ah3, al0, al1, al2, al3;
                LDSM_X4(ah0, ah1, ah2, ah3, aHiB + aOff[mf] + kbyte);
                LDSM_X4(al0, al1, al2, al3, aLoB + aOff[mf] + kbyte);
#pragma unroll
                for (int nf = 0; nf < 2; nf++) {
                    MMA_BF16(c_[mf][nf], ah0, ah1, ah2, ah3, bh0[nf], bh1[nf]);
                    MMA_BF16(c_[mf][nf], al0, al1, al2, al3, bh0[nf], bh1[nf]);
                    MMA_BF16(c_[mf][nf], ah0, ah1, ah2, ah3, bl0[nf], bl1[nf]);
                }
            }
        }
        __syncthreads();
        if (c + 1 < NCH) {
            streg();
            __syncthreads();
        }
    }

    // ---- epilogue ------------------------------------------------------------
#pragma unroll
    for (int mf = 0; mf < 2; mf++) {
        int rowa = m0 + wm * 32 + mf * 16 + g;
        int rowb = rowa + 8;
#pragma unroll
        for (int nf = 0; nf < 2; nf++) {
            int n = n0 + wn * 16 + nf * 8 + 2 * t;
            float v0 = c_[mf][nf][0], v1 = c_[mf][nf][1];
            float v2 = c_[mf][nf][2], v3 = c_[mf][nf][3];
            if (HAS_BIAS) {
                float bb0 = bias[n], bb1 = bias[n + 1];
                v0 += bb0; v1 += bb1; v2 += bb0; v3 += bb1;
            }
            if (RELU_OUT) {
                v0 = fmaxf(v0, 0.f); v1 = fmaxf(v1, 0.f);
                v2 = fmaxf(v2, 0.f); v3 = fmaxf(v3, 0.f);
            }
            if (SPLIT_OUT) {
                if (rowa < M) {
                    __nv_bfloat16 b0 = __float2bfloat16_rn(v0), b1 = __float2bfloat16_rn(v1);
                    *(uint32_t*)&Chi[(ll)rowa * KN + n] =
                        (uint32_t)__bfloat16_as_ushort(b0) | ((uint32_t)__bfloat16_as_ushort(b1) << 16);
                    *(uint32_t*)&Clo[(ll)rowa * KN + n] =
                        bpack(v0 - __bfloat162float(b0), v1 - __bfloat162float(b1));
                }
                if (rowb < M) {
                    __nv_bfloat16 b2 = __float2bfloat16_rn(v2), b3 = __float2bfloat16_rn(v3);
                    *(uint32_t*)&Chi[(ll)rowb * KN + n] =
                        (uint32_t)__bfloat16_as_ushort(b2) | ((uint32_t)__bfloat16_as_ushort(b3) << 16);
                    *(uint32_t*)&Clo[(ll)rowb * KN + n] =
                        bpack(v2 - __bfloat162float(b2), v3 - __bfloat162float(b3));
                }
            } else {
                if (rowa < M) *(float2*)&C[(ll)rowa * KN + n] = make_float2(v0, v1);
                if (rowb < M) *(float2*)&C[(ll)rowb * KN + n] = make_float2(v2, v3);
            }
        }
    }
}

static inline int smem_bytes(int KV) {
    return 2 * 64 * (KV * 2 + 16) + 2 * 64 * PADW * 4;
}

// ---------------- launch ------------------------------------------------------
extern "C" void kernel_launch(void* const* d_in, const int* in_sizes, int n_in,
                              void* d_out, int out_size) {
    const float* x     = (const float*)d_in[0];
    const void*  ei    = d_in[1];
    const float* W_lin = (const float*)d_in[2];
    const float* b_lin = (const float*)d_in[3];
    const float* Wl1   = (const float*)d_in[4];
    const float* bl1   = (const float*)d_in[5];
    const float* Wr1   = (const float*)d_in[6];
    const float* Wl2   = (const float*)d_in[7];
    const float* bl2   = (const float*)d_in[8];
    const float* Wr2   = (const float*)d_in[9];
    const float* W_cls = (const float*)d_in[10];
    float* out = (float*)d_out;

    int n_nodes = in_sizes[0] / IN_F;
    int E       = in_sizes[1] / 2;

    __nv_bfloat16 *xhi, *xlo, *h0hi, *h0lo, *h1hi, *h1lo, *h2hi, *h2lo, *mhi, *mlo;
    cudaGetSymbolAddress((void**)&xhi,  g_xhi);
    cudaGetSymbolAddress((void**)&xlo,  g_xlo);
    cudaGetSymbolAddress((void**)&h0hi, g_h0hi);
    cudaGetSymbolAddress((void**)&h0lo, g_h0lo);
    cudaGetSymbolAddress((void**)&h1hi, g_h1hi);
    cudaGetSymbolAddress((void**)&h1lo, g_h1lo);
    cudaGetSymbolAddress((void**)&h2hi, g_h2hi);
    cudaGetSymbolAddress((void**)&h2lo, g_h2lo);
    cudaGetSymbolAddress((void**)&mhi,  g_mhi);
    cudaGetSymbolAddress((void**)&mlo,  g_mlo);

    int nb_edges = (E + 255) / 256;
    int nb_agg   = (n_nodes + 7) / 8;
    int n4       = n_nodes * IN_F / 4;
    dim3 gH((n_nodes + 63) / 64, 2);   // KN=128 GEMMs
    dim3 gC((n_nodes + 63) / 64, 1);   // cls (KN=64)

    auto kProj = mma_gemm<HF, 256, false, true,  true,  true>;
    auto kSg1  = mma_gemm<HF, 256, true,  false, true,  true>;
    auto kSg2  = mma_gemm<HF, 256, true,  true,  true,  true>;
    auto kCls  = mma_gemm<NC, 128, false, false, false, false>;
    int sBig = smem_bytes(256);
    int sCls = smem_bytes(128);
    cudaFuncSetAttribute(kProj, cudaFuncAttributeMaxDynamicSharedMemorySize, sBig);
    cudaFuncSetAttribute(kSg1,  cudaFuncAttributeMaxDynamicSharedMemorySize, sBig);
    cudaFuncSetAttribute(kSg2,  cudaFuncAttributeMaxDynamicSharedMemorySize, sBig);
    cudaFuncSetAttribute(kCls,  cudaFuncAttributeMaxDynamicSharedMemorySize, sCls);

    // init (cnt zero + weight split), scatter, x split
    init_kernel<<<(TOTW + 255) / 256, 256>>>(W_lin, Wl1, Wr1, Wl2, Wr2, W_cls, n_nodes);
    scatter_kernel<<<nb_edges, 256>>>(ei, E, n_nodes);
    xsplit_kernel<<<(n4 + 255) / 256, 256>>>(x, n4);

    // h0 = relu(x @ W_lin^T + b_lin) -> split h0hi/h0lo
    kProj<<<gH, 256, sBig>>>(xhi, xlo, nullptr, nullptr, OFF_LIN, 0, b_lin,
                             nullptr, h0hi, h0lo, n_nodes);

    // sage1: mean = agg(h0hi) -> split; h1 = [mean|h0] @ [[Wl1];[Wr1]]^T + bl1
    agg_b16<<<nb_agg, 256>>>(h0hi, mhi, mlo, n_nodes);
    kSg1<<<gH, 256, sBig>>>(mhi, mlo, h0hi, h0lo, OFF_L1, OFF_R1, bl1,
                            nullptr, h1hi, h1lo, n_nodes);

    // sage2: mean = agg(h1hi); h2 = relu([mean|h1] @ [[Wl2];[Wr2]]^T + bl2) -> split
    agg_b16<<<nb_agg, 256>>>(h1hi, mhi, mlo, n_nodes);
    kSg2<<<gH, 256, sBig>>>(mhi, mlo, h1hi, h1lo, OFF_L2, OFF_R2, bl2,
                            nullptr, h2hi, h2lo, n_nodes);

    // out = relu(h2) @ W_cls^T  (h2 already relu'd + split)
    kCls<<<gC, 256, sCls>>>(h2hi, h2lo, nullptr, nullptr, OFF_CLS, 0, nullptr,
                            out, nullptr, nullptr, n_nodes);
}